// round 5
// baseline (speedup 1.0000x reference)
#include <cuda_runtime.h>
#include <cuda_bf16.h>
#include <cstdint>

typedef unsigned long long u64;

#define NP 16384
#define NG 16384
#define NY 16             // gt segments (grid.y)
#define SEG (NG / NY)     // 1024 gt per block
#define TILE 128
#define NT (SEG / TILE)   // 8 gt tiles per block (even: last buffer = 1)

#define INF_BITS 0x7f800000u
#define FLT_BIG 3.402823466e38f
#define NB_COMBINE 64

// Scratch (device globals, zero-initialized at module load).
// key = INF_BITS - float_bits(min): zero decodes to +inf, atomicMax == float-min.
// Combine kernel resets keys + counter for the next graph replay.
__device__ unsigned int g_key_pred[NP];
__device__ unsigned int g_key_gt[NG];
__device__ float        g_part[NB_COMBINE][4];
__device__ unsigned int g_ctr;

// ---------------------------------------------------------------------------
// Packed pair evaluation:
//   t2 = ax*gx + ay*gy + az*gz + gq   (per-half fp32 FMA, bit-exact)
//   v2 = t2 + pq
// Outputs the four scalar halves; mov.b64 {lo,hi} coalesces to the pair regs.
// ---------------------------------------------------------------------------
__device__ __forceinline__ void pair2(
    float& tlo, float& thi, float& vlo, float& vhi,
    u64 ax, u64 ay, u64 az, u64 pq,
    u64 gx, u64 gy, u64 gz, u64 gq)
{
    asm("{\n\t"
        ".reg .b64 t;\n\t"
        "fma.rn.f32x2 t, %6, %10, %11;\n\t"
        "fma.rn.f32x2 t, %5, %9, t;\n\t"
        "fma.rn.f32x2 t, %4, %8, t;\n\t"
        "mov.b64 {%0, %1}, t;\n\t"
        "add.rn.f32x2 t, t, %7;\n\t"
        "mov.b64 {%2, %3}, t;\n\t"
        "}"
        : "=f"(tlo), "=f"(thi), "=f"(vlo), "=f"(vhi)
        : "l"(ax), "l"(ay), "l"(az), "l"(pq),
          "l"(gx), "l"(gy), "l"(gz), "l"(gq));
}

__device__ __forceinline__ u64 dup2(float v) {
    u64 d; asm("mov.b64 %0, {%1, %1};" : "=l"(d) : "f"(v)); return d;
}

// ---------------------------------------------------------------------------
// Kernel 1: fused tiled pairwise-min, packed f32x2 inner loop.
// Block 256 threads: tx = tid&15, ty = tid>>4.
// Thread tile: 8 pred rows (ty+16*ii) x 8 gt cols ({2tx,2tx+1}+32*jj).
// Per 2 pairs: 3 FFMA2 + 1 FADD2 (fma pipe) + 4 FMNMX (alu pipe).
// Row mins tracked as lo/hi accumulators in t-space; folded once at end.
// ---------------------------------------------------------------------------
__global__ __launch_bounds__(256, 2)
void k_pairs(const float* __restrict__ pp, const float* __restrict__ gp) {
    __shared__ __align__(16) u64 sax[TILE], say[TILE], saz[TILE], spq[TILE]; // dup'd -2p, |p|^2
    __shared__ float spq1[TILE];                                            // scalar |p|^2
    __shared__ __align__(16) float sgx[2][TILE], sgy[2][TILE], sgz[2][TILE], sgq[2][TILE];
    __shared__ float sred[2][TILE * 17];

    const int tid = threadIdx.x;
    const int tx = tid & 15;
    const int ty = tid >> 4;
    const int bx = blockIdx.x;           // pred tile (0..127)
    const int by = blockIdx.y;           // gt segment (0..NY-1)
    const bool stager = (tid < TILE);

    if (stager) {
        int pi = bx * TILE + tid;
        float x = pp[3 * pi + 0];
        float y = pp[3 * pi + 1];
        float z = pp[3 * pi + 2];
        float q = x * x + y * y + z * z;
        sax[tid] = dup2(-2.0f * x);
        say[tid] = dup2(-2.0f * y);
        saz[tid] = dup2(-2.0f * z);
        spq[tid] = dup2(q);
        spq1[tid] = q;
        int gi = by * SEG + tid;
        float gx = gp[3 * gi + 0];
        float gy = gp[3 * gi + 1];
        float gz = gp[3 * gi + 2];
        sgx[0][tid] = gx; sgy[0][tid] = gy; sgz[0][tid] = gz;
        sgq[0][tid] = gx * gx + gy * gy + gz * gz;
    }
    __syncthreads();

    float rminLo[8], rminHi[8];
#pragma unroll
    for (int i = 0; i < 8; i++) { rminLo[i] = FLT_BIG; rminHi[i] = FLT_BIG; }

    for (int t = 0; t < NT; t++) {
        const int cur = t & 1;

        // prefetch next gt tile (latency hidden behind compute)
        float nx = 0.f, ny = 0.f, nz = 0.f;
        if (stager && t + 1 < NT) {
            int gi = by * SEG + (t + 1) * TILE + tid;
            nx = gp[3 * gi + 0]; ny = gp[3 * gi + 1]; nz = gp[3 * gi + 2];
        }

        // cache 8 gt columns as 4 packed pairs (LDS.64, 8B-aligned)
        u64 gx2[4], gy2[4], gz2[4], gq2[4];
#pragma unroll
        for (int jj = 0; jj < 4; jj++) {
            int c = 2 * tx + 32 * jj;
            gx2[jj] = *(const u64*)&sgx[cur][c];
            gy2[jj] = *(const u64*)&sgy[cur][c];
            gz2[jj] = *(const u64*)&sgz[cur][c];
            gq2[jj] = *(const u64*)&sgq[cur][c];
        }

        float cminA[4], cminB[4];
#pragma unroll
        for (int jj = 0; jj < 4; jj++) { cminA[jj] = FLT_BIG; cminB[jj] = FLT_BIG; }

#pragma unroll
        for (int ii = 0; ii < 8; ii++) {
            const int i = ty + 16 * ii;
            const u64 ax2 = sax[i], ay2 = say[i], az2 = saz[i], pq2 = spq[i];
#pragma unroll
            for (int jj = 0; jj < 4; jj++) {
                float tlo, thi, vlo, vhi;
                pair2(tlo, thi, vlo, vhi, ax2, ay2, az2, pq2,
                      gx2[jj], gy2[jj], gz2[jj], gq2[jj]);
                rminLo[ii] = fminf(rminLo[ii], tlo);
                rminHi[ii] = fminf(rminHi[ii], thi);
                cminA[jj]  = fminf(cminA[jj], vlo);
                cminB[jj]  = fminf(cminB[jj], vhi);
            }
        }

        // stash column mins (buffer 'cur')
#pragma unroll
        for (int jj = 0; jj < 4; jj++) {
            int c = 2 * tx + 32 * jj;
            sred[cur][c * 17 + ty]       = cminA[jj];
            sred[cur][(c + 1) * 17 + ty] = cminB[jj];
        }
        // commit prefetched gt tile into the other buffer
        if (stager && t + 1 < NT) {
            const int nb = cur ^ 1;
            sgx[nb][tid] = nx; sgy[nb][tid] = ny; sgz[nb][tid] = nz;
            sgq[nb][tid] = nx * nx + ny * ny + nz * nz;
        }
        __syncthreads();   // single barrier per tile

        // epilogue: column reduction + global min for tile t
        if (stager) {
            float m = sred[cur][tid * 17];
#pragma unroll
            for (int k = 1; k < 16; k++) m = fminf(m, sred[cur][tid * 17 + k]);
            m = fmaxf(m, 0.0f);
            atomicMax(&g_key_gt[by * SEG + t * TILE + tid], INF_BITS - __float_as_uint(m));
        }
    }

    // row reduction (last tile used sred[1]; rows use sred[0] — disjoint)
#pragma unroll
    for (int ii = 0; ii < 8; ii++)
        sred[0][(ty + 16 * ii) * 17 + tx] = fminf(rminLo[ii], rminHi[ii]);
    __syncthreads();
    if (stager) {
        float m = sred[0][tid * 17];
#pragma unroll
        for (int k = 1; k < 16; k++) m = fminf(m, sred[0][tid * 17 + k]);
        m = fmaxf(spq1[tid] + m, 0.0f);   // back to d2-space, clamp
        atomicMax(&g_key_pred[bx * TILE + tid], INF_BITS - __float_as_uint(m));
    }
}

// ---------------------------------------------------------------------------
// Kernel 2: weighted partial sums (64 blocks x 256 thr, 1 elem/thread) +
// last-block final combine. Deterministic fixed-order sums; resets scratch.
// ---------------------------------------------------------------------------
__global__ __launch_bounds__(256, 1)
void k_combine(const float* __restrict__ wp, const float* __restrict__ wg,
               float* __restrict__ out) {
    __shared__ float sh[4][8];
    __shared__ unsigned int s_ticket;
    const int b = blockIdx.x;
    const int tid = threadIdx.x;
    const int lane = tid & 31;
    const int wid = tid >> 5;
    const int i = b * 256 + tid;

    unsigned kp = g_key_pred[i];
    unsigned kg = g_key_gt[i];
    g_key_pred[i] = 0u;   // reset for next replay
    g_key_gt[i]   = 0u;
    float mp = __uint_as_float(INF_BITS - kp);
    float mg = __uint_as_float(INF_BITS - kg);
    float w1 = wp[i], w2 = wg[i];
    float a0 = w1 * mp, a1 = w1, a2 = w2 * mg, a3 = w2;

#pragma unroll
    for (int o = 16; o > 0; o >>= 1) {
        a0 += __shfl_down_sync(0xffffffffu, a0, o);
        a1 += __shfl_down_sync(0xffffffffu, a1, o);
        a2 += __shfl_down_sync(0xffffffffu, a2, o);
        a3 += __shfl_down_sync(0xffffffffu, a3, o);
    }
    if (lane == 0) { sh[0][wid] = a0; sh[1][wid] = a1; sh[2][wid] = a2; sh[3][wid] = a3; }
    __syncthreads();
    if (tid == 0) {
        float t0 = 0.f, t1 = 0.f, t2 = 0.f, t3 = 0.f;
#pragma unroll
        for (int w = 0; w < 8; w++) { t0 += sh[0][w]; t1 += sh[1][w]; t2 += sh[2][w]; t3 += sh[3][w]; }
        g_part[b][0] = t0; g_part[b][1] = t1; g_part[b][2] = t2; g_part[b][3] = t3;
        __threadfence();
        s_ticket = atomicAdd(&g_ctr, 1u);
    }
    __syncthreads();

    if (s_ticket == NB_COMBINE - 1) {     // last-arriving block finalizes
        __threadfence();
        if (tid < NB_COMBINE) {
            volatile float (*part)[4] = g_part;
            float p0 = part[tid][0], p1 = part[tid][1];
            float p2 = part[tid][2], p3 = part[tid][3];
#pragma unroll
            for (int o = 16; o > 0; o >>= 1) {
                p0 += __shfl_down_sync(0xffffffffu, p0, o);
                p1 += __shfl_down_sync(0xffffffffu, p1, o);
                p2 += __shfl_down_sync(0xffffffffu, p2, o);
                p3 += __shfl_down_sync(0xffffffffu, p3, o);
            }
            if (lane == 0) {
                sh[0][wid] = p0; sh[1][wid] = p1; sh[2][wid] = p2; sh[3][wid] = p3;
            }
        }
        __syncthreads();
        if (tid == 0) {
            float s0 = sh[0][0] + sh[0][1];
            float s1 = sh[1][0] + sh[1][1];
            float s2 = sh[2][0] + sh[2][1];
            float s3 = sh[3][0] + sh[3][1];
            out[0] = s0 / fmaxf(s1, 1e-9f) + s2 / fmaxf(s3, 1e-9f);
            g_ctr = 0u;   // reset for next replay
        }
    }
}

// ---------------------------------------------------------------------------
extern "C" void kernel_launch(void* const* d_in, const int* in_sizes, int n_in,
                              void* d_out, int out_size) {
    const float* pred = (const float*)d_in[0];   // (P,3)
    const float* gt   = (const float*)d_in[1];   // (G,3)
    const float* wp   = (const float*)d_in[2];   // (P,)
    const float* wg   = (const float*)d_in[3];   // (G,)
    float* out = (float*)d_out;

    dim3 grid(NP / TILE, NY);
    k_pairs<<<grid, 256>>>(pred, gt);
    k_combine<<<NB_COMBINE, 256>>>(wp, wg, out);
}